// round 9
// baseline (speedup 1.0000x reference)
#include <cuda_runtime.h>
#include <float.h>
#include <stdint.h>

// Problem constants
#define KC      1024        // num codes
#define DD      64          // embedding dim
#define NTOK    65536       // 16*64*64 tokens
#define HW      4096        // 64*64
#define DECAYF  0.99f
#define OMDF    0.01f       // 1 - decay
#define COMMITF 0.25f
#define EPSF    1e-5f

// Output layout (flattened tuple, in reference return order)
#define OFF_LOSS 0ull
#define OFF_Q    1ull
#define OFF_ENC  (1ull + 4194304ull)
#define OFF_EMB  (OFF_ENC + 67108864ull)
#define OFF_CS   (OFF_EMB + 65536ull)
#define OFF_EMA  (OFF_CS + 1024ull)

// Dynamic smem layout (bytes)
#define SM_XS     0        // 4096 u64  (32 dpairs x 128 tokens)  32768 B
#define SM_ES     32768    // 128 codes x 68 floats (64 used)     34816 B
#define SM_NORM   67584    // 128 floats
#define SM_SCORE  68096    // 128 tokens x 8 tx floats            4096 B
#define SM_SIDX   72192    // 128 x 8 ints                        4096 B
#define SM_IDXF   76288    // 128 ints
#define SM_RED    76800    // 8 floats
#define SM_TOTAL  76832

// Scratch (no allocations allowed -> __device__ globals)
__device__ float g_counts[KC];
__device__ float g_dw[KC * DD];
__device__ float g_enorm[KC];
__device__ float g_loss;
__device__ float g_nsum;

// ---- packed f32x2 helpers ----
__device__ __forceinline__ unsigned long long pack2(float a, float b) {
    unsigned long long v;
    asm("mov.b64 %0, {%1, %2};" : "=l"(v) : "f"(a), "f"(b));
    return v;
}
__device__ __forceinline__ float2 unpack2(unsigned long long v) {
    float2 r;
    asm("mov.b64 {%0, %1}, %2;" : "=f"(r.x), "=f"(r.y) : "l"(v));
    return r;
}
#define FFMA2(d, a, b, c) \
    asm("fma.rn.f32x2 %0, %1, %2, %3;" : "=l"(d) : "l"(a), "l"(b), "l"(c))

// ================= K0: zero scratch + codebook norms =================
__global__ void vq_init(const float* __restrict__ E) {
    int i = blockIdx.x * blockDim.x + threadIdx.x;   // 65536 threads
    g_dw[i] = 0.f;
    if (i < KC) {
        g_counts[i] = 0.f;
        const float4* e4 = (const float4*)(E + (size_t)i * DD);
        float s = 0.f;
#pragma unroll
        for (int q = 0; q < 16; q++) {
            float4 v = e4[q];
            s += v.x * v.x + v.y * v.y + v.z * v.z + v.w * v.w;
        }
        g_enorm[i] = s;
    }
    if (i == 0) g_loss = 0.f;
}

// ================= K1: main — register-tiled argmin GEMM + outputs ===========
// 512 CTAs x 256 threads; CTA owns 128 tokens. Thread (ty,tx): ty=t>>3 token
// group (4 tokens), tx=t&7 code group. 4x4 accumulator tile in packed f32x2.
__global__ __launch_bounds__(256, 2) void vq_main(
    const float* __restrict__ x,    // NCHW [16,64,64,64]
    const float* __restrict__ E,    // [1024,64]
    float* __restrict__ out)
{
    extern __shared__ char smem[];
    unsigned long long* xs = (unsigned long long*)(smem + SM_XS);
    float* es    = (float*)(smem + SM_ES);
    float* sNorm = (float*)(smem + SM_NORM);
    float* sScore= (float*)(smem + SM_SCORE);
    int*   sSIdx = (int*)  (smem + SM_SIDX);
    int*   sIdxF = (int*)  (smem + SM_IDXF);
    float* sRed  = (float*)(smem + SM_RED);

    const int t   = threadIdx.x;     // 0..255
    const int tx  = t & 7;
    const int ty  = t >> 3;          // 0..31
    const int n0  = blockIdx.x * 128;
    const int b   = n0 >> 12;        // /4096
    const int hw0 = n0 & 4095;

    // ---- stage x tile into smem, dpair-major: xs[dp*128 + tok] ----
#pragma unroll
    for (int i = 0; i < 16; i++) {
        int idx = t + i * 256;           // 0..4095 == dp*128 + tok
        int dp  = idx >> 7;
        int tok = idx & 127;
        const float* xp = x + ((size_t)b * DD + 2 * dp) * HW + hw0 + tok;
        xs[idx] = pack2(xp[0], xp[HW]);
    }

    float best[4];
    int   bidx[4];
#pragma unroll
    for (int i = 0; i < 4; i++) { best[i] = FLT_MAX; bidx[i] = 0; }

    // ---- 8 chunks of 128 codes ----
    for (int ch = 0; ch < 8; ch++) {
        __syncthreads();   // protect es/sNorm from previous chunk's readers
        const float4* src = (const float4*)(E + (size_t)ch * 128 * DD);
#pragma unroll
        for (int i2 = 0; i2 < 8; i2++) {
            int f = t + i2 * 256;            // 2048 float4 of the chunk
            int code = f >> 4, q = f & 15;
            *(float4*)&es[code * 68 + q * 4] = src[f];   // padded rows: 68 floats
        }
        if (t < 128) sNorm[t] = g_enorm[ch * 128 + t];
        __syncthreads();

        for (int cc = 0; cc < 4; cc++) {          // 32 codes per pass
            unsigned long long acc[4][4];
#pragma unroll
            for (int i = 0; i < 4; i++)
#pragma unroll
                for (int j = 0; j < 4; j++) acc[i][j] = 0ull;

            const int cbase = cc * 32 + tx;       // code(j) = cbase + j*8

#pragma unroll 4
            for (int dq = 0; dq < 16; dq++) {     // d-quad = 4 dims = 2 dpairs
                unsigned long long xa0[4], xa1[4], eb0[4], eb1[4];
#pragma unroll
                for (int k = 0; k < 2; k++) {
                    ulonglong2 v0 = *(const ulonglong2*)&xs[(2 * dq)     * 128 + ty * 4 + 2 * k];
                    ulonglong2 v1 = *(const ulonglong2*)&xs[(2 * dq + 1) * 128 + ty * 4 + 2 * k];
                    xa0[2 * k] = v0.x; xa0[2 * k + 1] = v0.y;
                    xa1[2 * k] = v1.x; xa1[2 * k + 1] = v1.y;
                }
#pragma unroll
                for (int j = 0; j < 4; j++) {
                    ulonglong2 ev = *(const ulonglong2*)&es[(cbase + j * 8) * 68 + dq * 4];
                    eb0[j] = ev.x; eb1[j] = ev.y;
                }
#pragma unroll
                for (int i = 0; i < 4; i++)
#pragma unroll
                    for (int j = 0; j < 4; j++) {
                        FFMA2(acc[i][j], xa0[i], eb0[j], acc[i][j]);
                        FFMA2(acc[i][j], xa1[i], eb1[j], acc[i][j]);
                    }
            }

            // scores + per-token best (codes ascend within thread: strict <)
#pragma unroll
            for (int j = 0; j < 4; j++) {
                const int code = cbase + j * 8;
                const float nrm = sNorm[code];
#pragma unroll
                for (int i = 0; i < 4; i++) {
                    float2 f = unpack2(acc[i][j]);
                    float score = nrm - 2.0f * (f.x + f.y);
                    if (score < best[i]) { best[i] = score; bidx[i] = ch * 128 + code; }
                }
            }
        }
    }

    // ---- cross-tx argmin reduction per token ----
#pragma unroll
    for (int i = 0; i < 4; i++) {
        sScore[(ty * 4 + i) * 8 + tx] = best[i];
        sSIdx [(ty * 4 + i) * 8 + tx] = bidx[i];
    }
    __syncthreads();
    if (t < 128) {
        float bsc = sScore[t * 8];
        int   bid = sSIdx [t * 8];
#pragma unroll
        for (int u = 1; u < 8; u++) {
            float s = sScore[t * 8 + u];
            int   d = sSIdx [t * 8 + u];
            if (s < bsc || (s == bsc && d < bid)) { bsc = s; bid = d; }
        }
        sIdxF[t] = bid;
        atomicAdd(&g_counts[bid], 1.0f);
    }
    __syncthreads();   // publish sIdxF to all 256 threads

    // ---- per-token epilogue, 2 threads per token: q out (NCHW), loss, dw ----
    {
        const int tok  = t & 127;
        const int half = t >> 7;          // 0 or 1: d-quads [half*8, half*8+8)
        const int bid  = sIdxF[tok];
        const float4* erow = (const float4*)(E + (size_t)bid * DD);
        float* qout = out + OFF_Q + ((size_t)b * DD) * HW + hw0 + tok;
        float* dwp  = g_dw + (size_t)bid * DD;
        float lsum = 0.f;
#pragma unroll
        for (int qq = 0; qq < 8; qq++) {
            int q4 = half * 8 + qq;
            float4 ev = __ldg(erow + q4);      // scattered, L2-hot (E = 256KB)
            float2 xa = unpack2(xs[(2 * q4)     * 128 + tok]);
            float2 xb = unpack2(xs[(2 * q4 + 1) * 128 + tok]);
            int d = q4 * 4;
            qout[(size_t)(d + 0) * HW] = ev.x;
            qout[(size_t)(d + 1) * HW] = ev.y;
            qout[(size_t)(d + 2) * HW] = ev.z;
            qout[(size_t)(d + 3) * HW] = ev.w;
            float d0 = ev.x - xa.x, d1 = ev.y - xa.y;
            float d2 = ev.z - xb.x, d3 = ev.w - xb.y;
            lsum += d0 * d0 + d1 * d1 + d2 * d2 + d3 * d3;
            atomicAdd(dwp + d + 0, xa.x);
            atomicAdd(dwp + d + 1, xa.y);
            atomicAdd(dwp + d + 2, xb.x);
            atomicAdd(dwp + d + 3, xb.y);
        }
        // block-reduce commitment-loss partial (8 warps)
#pragma unroll
        for (int o = 16; o > 0; o >>= 1) lsum += __shfl_xor_sync(0xffffffffu, lsum, o);
        if ((t & 31) == 0) sRed[t >> 5] = lsum;
        __syncthreads();
        if (t == 0) {
            float s = 0.f;
#pragma unroll
            for (int w = 0; w < 8; w++) s += sRed[w];
            atomicAdd(&g_loss, s);
        }
    }

    // ---- cooperative one-hot encodings write: 128 tokens x 1024 cols ----
    // out + OFF_ENC is offset 1 float mod 16B, so each GLOBAL token row
    // (n0+tok)*1024 is vector-alignable only from col 3. Per token:
    // cols [3,1023) as 255 float4, cols {0,1,2,1023} scalar.
    {
        float* encb = out + OFF_ENC;
#pragma unroll 4
        for (int i = t; i < 128 * 256; i += 256) {
            int tok = i >> 8;
            int q   = i & 255;
            int id  = sIdxF[tok];
            float* row = encb + (size_t)(n0 + tok) * KC;   // GLOBAL token row
            if (q < 255) {
                int c0 = 3 + q * 4;
                float4 v;
                v.x = (float)(c0 + 0 == id);
                v.y = (float)(c0 + 1 == id);
                v.z = (float)(c0 + 2 == id);
                v.w = (float)(c0 + 3 == id);
                __stcs((float4*)(row + c0), v);
            } else {
                __stcs(row + 0,    (float)(id == 0));
                __stcs(row + 1,    (float)(id == 1));
                __stcs(row + 2,    (float)(id == 2));
                __stcs(row + 1023, (float)(id == 1023));
            }
        }
    }
}

// ================= K2: EMA cluster-size raw + global sum n =================
__global__ void vq_reduce(const float* __restrict__ ema_cs) {
    int k = threadIdx.x;   // 1024 threads, 1 block
    float raw = ema_cs[k] * DECAYF + OMDF * g_counts[k];
    g_counts[k] = raw;     // reuse scratch for raw new_cs
    __shared__ float wsum[32];
    float s = raw;
#pragma unroll
    for (int o = 16; o > 0; o >>= 1) s += __shfl_xor_sync(0xffffffffu, s, o);
    if ((k & 31) == 0) wsum[k >> 5] = s;
    __syncthreads();
    if (k < 32) {
        float v = wsum[k];
#pragma unroll
        for (int o = 16; o > 0; o >>= 1) v += __shfl_xor_sync(0xffffffffu, v, o);
        if (k == 0) g_nsum = v;
    }
}

// ================= K3: finalize codebook outputs + loss =================
__global__ void vq_final(const float* __restrict__ ema_w, float* __restrict__ out) {
    int i = blockIdx.x * blockDim.x + threadIdx.x;   // 65536 = K*D
    int k = i >> 6;
    int d = i & 63;
    float n   = g_nsum;
    float raw = g_counts[k];
    float cs  = (raw + EPSF) / (n + (float)KC * EPSF) * n;  // Laplace smoothing
    float nw  = ema_w[i] * DECAYF + OMDF * g_dw[i];
    out[OFF_EMA + i] = nw;
    out[OFF_EMB + i] = nw / cs;
    if (d == 0) out[OFF_CS + k] = cs;
    if (i == 0) out[OFF_LOSS] = COMMITF * g_loss / 4194304.0f;
}

// ================= launch =================
extern "C" void kernel_launch(void* const* d_in, const int* in_sizes, int n_in,
                              void* d_out, int out_size) {
    const float* x      = (const float*)d_in[0];   // [16,64,64,64]
    const float* E      = (const float*)d_in[1];   // [1024,64]
    const float* ema_cs = (const float*)d_in[2];   // [1024]
    const float* ema_w  = (const float*)d_in[3];   // [1024,64]
    float* out = (float*)d_out;

    cudaFuncSetAttribute(vq_main, cudaFuncAttributeMaxDynamicSharedMemorySize, SM_TOTAL);

    vq_init<<<256, 256>>>(E);
    vq_main<<<NTOK / 128, 256, SM_TOTAL>>>(x, E, out);
    vq_reduce<<<1, 1024>>>(ema_cs);
    vq_final<<<64, 1024>>>(ema_w, out);
}

// round 10
// speedup vs baseline: 1.0881x; 1.0881x over previous
#include <cuda_runtime.h>
#include <float.h>
#include <stdint.h>

// Problem constants
#define KC      1024        // num codes
#define DD      64          // embedding dim
#define NTOK    65536       // 16*64*64 tokens
#define HW      4096        // 64*64
#define DECAYF  0.99f
#define OMDF    0.01f       // 1 - decay
#define COMMITF 0.25f
#define EPSF    1e-5f

// Output layout (flattened tuple, in reference return order)
#define OFF_LOSS 0ull
#define OFF_Q    1ull
#define OFF_ENC  (1ull + 4194304ull)
#define OFF_EMB  (OFF_ENC + 67108864ull)
#define OFF_CS   (OFF_EMB + 65536ull)
#define OFF_EMA  (OFF_CS + 1024ull)

// Dynamic smem layout (bytes). Post-GEMM buffers ALIAS the es region (dead then).
#define SM_XS     0        // 4096 u64  (32 dpairs x 128 tokens)  32768 B
#define SM_ES     32768    // 128 codes x 68 floats (64 used)     34816 B
#define SM_NORM   67584    // 128 floats                          512 B
#define SM_TOTAL  68096
// aliases into SM_ES after GEMM completes:
#define SMA_SCORE (SM_ES)            // 128 tokens x 8 floats  = 4096 B
#define SMA_SIDX  (SM_ES + 4096)     // 128 x 8 ints           = 4096 B
#define SMA_IDXF  (SM_ES + 8192)     // 128 ints               = 512 B
#define SMA_RED   (SM_ES + 8704)     // 4 floats

// Scratch (no allocations allowed -> __device__ globals)
__device__ float g_counts[KC];
__device__ float g_dw[KC * DD];
__device__ float g_enorm[KC];
__device__ float g_loss;
__device__ float g_nsum;

// ---- packed f32x2 helpers ----
__device__ __forceinline__ unsigned long long pack2(float a, float b) {
    unsigned long long v;
    asm("mov.b64 %0, {%1, %2};" : "=l"(v) : "f"(a), "f"(b));
    return v;
}
__device__ __forceinline__ float2 unpack2(unsigned long long v) {
    float2 r;
    asm("mov.b64 {%0, %1}, %2;" : "=f"(r.x), "=f"(r.y) : "l"(v));
    return r;
}
#define FFMA2(d, a, b, c) \
    asm("fma.rn.f32x2 %0, %1, %2, %3;" : "=l"(d) : "l"(a), "l"(b), "l"(c))

// ================= K0: zero scratch + codebook norms =================
__global__ void vq_init(const float* __restrict__ E) {
    int i = blockIdx.x * blockDim.x + threadIdx.x;   // 65536 threads
    g_dw[i] = 0.f;
    if (i < KC) {
        g_counts[i] = 0.f;
        const float4* e4 = (const float4*)(E + (size_t)i * DD);
        float s = 0.f;
#pragma unroll
        for (int q = 0; q < 16; q++) {
            float4 v = e4[q];
            s += v.x * v.x + v.y * v.y + v.z * v.z + v.w * v.w;
        }
        g_enorm[i] = s;
    }
    if (i == 0) g_loss = 0.f;
}

// ================= K1: main — register-tiled argmin GEMM + outputs ===========
// 512 CTAs x 128 threads; CTA owns 128 tokens. Thread (ty,tx): ty=t>>3 token
// group (8 tokens), tx=t&7 code group. 8x4 accumulator tile in packed f32x2.
__global__ __launch_bounds__(128, 3) void vq_main(
    const float* __restrict__ x,    // NCHW [16,64,64,64]
    const float* __restrict__ E,    // [1024,64]
    float* __restrict__ out)
{
    extern __shared__ char smem[];
    unsigned long long* xs = (unsigned long long*)(smem + SM_XS);
    float* es    = (float*)(smem + SM_ES);
    float* sNorm = (float*)(smem + SM_NORM);
    float* sScore= (float*)(smem + SMA_SCORE);   // aliases es (post-GEMM only)
    int*   sSIdx = (int*)  (smem + SMA_SIDX);
    int*   sIdxF = (int*)  (smem + SMA_IDXF);
    float* sRed  = (float*)(smem + SMA_RED);

    const int t   = threadIdx.x;
    const int tx  = t & 7;
    const int ty  = t >> 3;
    const int n0  = blockIdx.x * 128;
    const int b   = n0 >> 12;          // /4096
    const int hw0 = n0 & 4095;

    // ---- stage x tile into smem, dpair-major: xs[dp*128 + tok] ----
    const float* xg = x + ((size_t)b * DD) * HW + hw0 + t;
#pragma unroll
    for (int dp = 0; dp < 32; dp++) {
        float lo = __ldcs(&xg[(size_t)(2 * dp) * HW]);      // read-once stream
        float hi = __ldcs(&xg[(size_t)(2 * dp + 1) * HW]);
        xs[dp * 128 + t] = pack2(lo, hi);
    }

    float best[8];
    int   bidx[8];
#pragma unroll
    for (int i = 0; i < 8; i++) { best[i] = FLT_MAX; bidx[i] = 0; }

    // ---- 8 chunks of 128 codes ----
    for (int ch = 0; ch < 8; ch++) {
        __syncthreads();   // protect es/sNorm from previous chunk's readers
        const float4* src = (const float4*)(E + (size_t)ch * 128 * DD);
#pragma unroll
        for (int i2 = 0; i2 < 16; i2++) {
            int f = t + i2 * 128;            // 2048 float4 of the chunk
            int code = f >> 4, q = f & 15;
            *(float4*)&es[code * 68 + q * 4] = src[f];   // padded rows: 68 floats
        }
        sNorm[t] = g_enorm[ch * 128 + t];
        __syncthreads();

        for (int cc = 0; cc < 4; cc++) {          // 32 codes per pass
            unsigned long long acc[8][4];
#pragma unroll
            for (int i = 0; i < 8; i++)
#pragma unroll
                for (int j = 0; j < 4; j++) acc[i][j] = 0ull;

            const int cbase = cc * 32 + tx;       // code(j) = cbase + j*8

#pragma unroll 4
            for (int dq = 0; dq < 16; dq++) {     // d-quad = 4 dims = 2 dpairs
                unsigned long long xa0[8], xa1[8], eb0[4], eb1[4];
#pragma unroll
                for (int k = 0; k < 4; k++) {
                    ulonglong2 v0 = *(const ulonglong2*)&xs[(2 * dq)     * 128 + ty * 8 + 2 * k];
                    ulonglong2 v1 = *(const ulonglong2*)&xs[(2 * dq + 1) * 128 + ty * 8 + 2 * k];
                    xa0[2 * k] = v0.x; xa0[2 * k + 1] = v0.y;
                    xa1[2 * k] = v1.x; xa1[2 * k + 1] = v1.y;
                }
#pragma unroll
                for (int j = 0; j < 4; j++) {
                    ulonglong2 ev = *(const ulonglong2*)&es[(cbase + j * 8) * 68 + dq * 4];
                    eb0[j] = ev.x; eb1[j] = ev.y;
                }
#pragma unroll
                for (int i = 0; i < 8; i++)
#pragma unroll
                    for (int j = 0; j < 4; j++) {
                        FFMA2(acc[i][j], xa0[i], eb0[j], acc[i][j]);
                        FFMA2(acc[i][j], xa1[i], eb1[j], acc[i][j]);
                    }
            }

            // scores + per-token best (codes ascend within thread: strict <)
#pragma unroll
            for (int j = 0; j < 4; j++) {
                const int code = cbase + j * 8;
                const float nrm = sNorm[code];
#pragma unroll
                for (int i = 0; i < 8; i++) {
                    float2 f = unpack2(acc[i][j]);
                    float score = nrm - 2.0f * (f.x + f.y);
                    if (score < best[i]) { best[i] = score; bidx[i] = ch * 128 + code; }
                }
            }
        }
    }

    // ---- cross-tx argmin reduction per token (buffers alias dead es) ----
    __syncthreads();   // all GEMM reads of es done before aliased writes
#pragma unroll
    for (int i = 0; i < 8; i++) {
        sScore[(ty * 8 + i) * 8 + tx] = best[i];
        sSIdx [(ty * 8 + i) * 8 + tx] = bidx[i];
    }
    __syncthreads();
    float bsc = sScore[t * 8];
    int   bid = sSIdx [t * 8];
#pragma unroll
    for (int u = 1; u < 8; u++) {
        float s = sScore[t * 8 + u];
        int   d = sSIdx [t * 8 + u];
        if (s < bsc || (s == bsc && d < bid)) { bsc = s; bid = d; }
    }
    sIdxF[t] = bid;
    atomicAdd(&g_counts[bid], 1.0f);

    // ---- per-token epilogue: quantized out (NCHW), loss partial, dw scatter ----
    const float4* erow = (const float4*)(E + (size_t)bid * DD);
    float* qout = out + OFF_Q + ((size_t)b * DD) * HW + hw0 + t;
    float* dwp  = g_dw + (size_t)bid * DD;
    float lsum = 0.f;
#pragma unroll
    for (int q4 = 0; q4 < 16; q4++) {
        float4 ev = __ldg(erow + q4);      // scattered, L2-hot (E = 256KB)
        float2 xa = unpack2(xs[(2 * q4)     * 128 + t]);
        float2 xb = unpack2(xs[(2 * q4 + 1) * 128 + t]);
        int d = q4 * 4;
        __stcs(&qout[(size_t)(d + 0) * HW], ev.x);
        __stcs(&qout[(size_t)(d + 1) * HW], ev.y);
        __stcs(&qout[(size_t)(d + 2) * HW], ev.z);
        __stcs(&qout[(size_t)(d + 3) * HW], ev.w);
        float d0 = ev.x - xa.x, d1 = ev.y - xa.y;
        float d2 = ev.z - xb.x, d3 = ev.w - xb.y;
        lsum += d0 * d0 + d1 * d1 + d2 * d2 + d3 * d3;
        atomicAdd(dwp + d + 0, xa.x);
        atomicAdd(dwp + d + 1, xa.y);
        atomicAdd(dwp + d + 2, xb.x);
        atomicAdd(dwp + d + 3, xb.y);
    }

    // block-reduce commitment-loss partial
#pragma unroll
    for (int o = 16; o > 0; o >>= 1) lsum += __shfl_xor_sync(0xffffffffu, lsum, o);
    if ((t & 31) == 0) sRed[t >> 5] = lsum;
    __syncthreads();
    if (t == 0) atomicAdd(&g_loss, sRed[0] + sRed[1] + sRed[2] + sRed[3]);

    // ---- cooperative one-hot encodings write: 128 tokens x 1024 cols ----
    // out + OFF_ENC is offset 1 float mod 16B, so each GLOBAL token row
    // (n0+tok)*1024 is vector-alignable only from col 3. Per token:
    // cols [3,1023) as 255 float4, cols {0,1,2,1023} scalar.
    {
        float* encb = out + OFF_ENC;
#pragma unroll 4
        for (int i = t; i < 128 * 256; i += 128) {
            int tok = i >> 8;
            int q   = i & 255;
            int id  = sIdxF[tok];
            float* row = encb + (size_t)(n0 + tok) * KC;   // GLOBAL token row
            if (q < 255) {
                int c0 = 3 + q * 4;
                float4 v;
                v.x = (float)(c0 + 0 == id);
                v.y = (float)(c0 + 1 == id);
                v.z = (float)(c0 + 2 == id);
                v.w = (float)(c0 + 3 == id);
                __stcs((float4*)(row + c0), v);
            } else {
                __stcs(row + 0,    (float)(id == 0));
                __stcs(row + 1,    (float)(id == 1));
                __stcs(row + 2,    (float)(id == 2));
                __stcs(row + 1023, (float)(id == 1023));
            }
        }
    }
}

// ================= K2: EMA cluster-size raw + global sum n =================
__global__ void vq_reduce(const float* __restrict__ ema_cs) {
    int k = threadIdx.x;   // 1024 threads, 1 block
    float raw = ema_cs[k] * DECAYF + OMDF * g_counts[k];
    g_counts[k] = raw;     // reuse scratch for raw new_cs
    __shared__ float wsum[32];
    float s = raw;
#pragma unroll
    for (int o = 16; o > 0; o >>= 1) s += __shfl_xor_sync(0xffffffffu, s, o);
    if ((k & 31) == 0) wsum[k >> 5] = s;
    __syncthreads();
    if (k < 32) {
        float v = wsum[k];
#pragma unroll
        for (int o = 16; o > 0; o >>= 1) v += __shfl_xor_sync(0xffffffffu, v, o);
        if (k == 0) g_nsum = v;
    }
}

// ================= K3: finalize codebook outputs + loss =================
__global__ void vq_final(const float* __restrict__ ema_w, float* __restrict__ out) {
    int i = blockIdx.x * blockDim.x + threadIdx.x;   // 65536 = K*D
    int k = i >> 6;
    int d = i & 63;
    float n   = g_nsum;
    float raw = g_counts[k];
    float cs  = (raw + EPSF) / (n + (float)KC * EPSF) * n;  // Laplace smoothing
    float nw  = ema_w[i] * DECAYF + OMDF * g_dw[i];
    out[OFF_EMA + i] = nw;
    out[OFF_EMB + i] = nw / cs;
    if (d == 0) out[OFF_CS + k] = cs;
    if (i == 0) out[OFF_LOSS] = COMMITF * g_loss / 4194304.0f;
}

// ================= launch =================
extern "C" void kernel_launch(void* const* d_in, const int* in_sizes, int n_in,
                              void* d_out, int out_size) {
    const float* x      = (const float*)d_in[0];   // [16,64,64,64]
    const float* E      = (const float*)d_in[1];   // [1024,64]
    const float* ema_cs = (const float*)d_in[2];   // [1024]
    const float* ema_w  = (const float*)d_in[3];   // [1024,64]
    float* out = (float*)d_out;

    cudaFuncSetAttribute(vq_main, cudaFuncAttributeMaxDynamicSharedMemorySize, SM_TOTAL);

    vq_init<<<256, 256>>>(E);
    vq_main<<<NTOK / 128, 128, SM_TOTAL>>>(x, E, out);
    vq_reduce<<<1, 1024>>>(ema_cs);
    vq_final<<<64, 1024>>>(ema_w, out);
}